// round 6
// baseline (speedup 1.0000x reference)
#include <cuda_runtime.h>
#include <cuda_bf16.h>
#include <cstdint>

// Embedding gather: out[token, :] = W[:, ids[token]], W row-major [D_MODEL, VOCAB].
// R6: R5's 4-stage pipeline with the alignment bug fixed -- VOCAB is ODD, so
// global row starts alternate 4B/8B alignment; only 4B cp.async is legal.
// 4 stages x TILE_D=32, one barrier per chunk, PAD=65 conflict-free.

#define VOCAB     50257
#define D_MODEL   1024
#define N_TOK     (4 * 4096)

#define TILE_C    64
#define TILE_BITS 6
#define N_TILES   ((VOCAB + TILE_C - 1) / TILE_C)   // 786
#define TILE_D    32                                // rows per chunk (= warp size)
#define N_CHUNK   (D_MODEL / TILE_D)                // 32
#define STAGES    4
#define PAD       (TILE_C + 1)                      // 65: conflict-free column reads
#define STAGE_ELEMS (TILE_D * PAD)                  // 2080 floats = 8320 B

// Scratch (device globals; no allocation allowed).
__device__ int g_start[N_TILES + 1];
__device__ int g_slots[N_TOK];    // (col_in_tile << 16) | token_index

// ---------------- fused prep: hist + scan + scatter, one block ----------------
__global__ __launch_bounds__(1024, 1)
void prep_kernel(const int* __restrict__ ids) {
    __shared__ int s_hist[1024];
    __shared__ int s_off[N_TILES];
    const int t = threadIdx.x;

    s_hist[t] = 0;
    __syncthreads();

    int my_id[N_TOK / 1024];
    #pragma unroll
    for (int i = 0; i < N_TOK / 1024; i++) {
        my_id[i] = ids[t + i * 1024];
        atomicAdd(&s_hist[my_id[i] >> TILE_BITS], 1);
    }
    __syncthreads();

    const int mine = s_hist[t];
    #pragma unroll
    for (int off = 1; off < 1024; off <<= 1) {
        int v = (t >= off) ? s_hist[t - off] : 0;
        __syncthreads();
        s_hist[t] += v;
        __syncthreads();
    }
    const int excl = s_hist[t] - mine;
    if (t <= N_TILES) g_start[t] = excl;
    if (t < N_TILES)  s_off[t]  = excl;
    __syncthreads();

    #pragma unroll
    for (int i = 0; i < N_TOK / 1024; i++) {
        const int id  = my_id[i];
        const int pos = atomicAdd(&s_off[id >> TILE_BITS], 1);
        g_slots[pos] = ((id & (TILE_C - 1)) << 16) | (t + i * 1024);
    }
}

// ---------------- cp.async helpers ----------------
__device__ __forceinline__ void cp_async4(uint32_t saddr, const void* gptr) {
    asm volatile("cp.async.ca.shared.global [%0], [%1], 4;\n"
                 :: "r"(saddr), "l"(gptr));
}
__device__ __forceinline__ void cp_commit() {
    asm volatile("cp.async.commit_group;\n");
}
template <int N>
__device__ __forceinline__ void cp_wait() {
    asm volatile("cp.async.wait_group %0;\n" :: "n"(N));
}

// ---------------- gather: one block per 64-column tile ----------------
__global__ __launch_bounds__(256, 6)
void gather_tile_kernel(const float* __restrict__ W, float* __restrict__ out) {
    const int tile = blockIdx.x;
    const int slot_start = g_start[tile];
    const int slot_end   = g_start[tile + 1];
    if (slot_start >= slot_end) return;

    __shared__ float buf[STAGES * STAGE_ELEMS];

    const int tid  = threadIdx.x;
    const int lane = tid & 31;
    const int wid  = tid >> 5;                 // 8 warps
    const int c0   = tile * TILE_C;

    // Load mapping: 4B per thread, 64 cols x 4 rows per pass, 8 passes/chunk.
    const int lc = tid & (TILE_C - 1);         // 0..63
    const int lr = tid >> TILE_BITS;           // 0..3
    const int gcol = c0 + lc;
    const bool cvalid = (gcol < VOCAB);        // only last tile has invalid cols
    const float* __restrict__ col_base = W + gcol;

    const uint32_t sbase = (uint32_t)__cvta_generic_to_shared(&buf[0]);

    auto issue_chunk = [&](int c) {
        const uint32_t so = (uint32_t)((c & (STAGES - 1)) * STAGE_ELEMS * 4);
        if (cvalid) {
            #pragma unroll
            for (int p = 0; p < TILE_D / 4; p++) {   // 8 passes of 4 rows
                const int row = p * 4 + lr;
                cp_async4(sbase + so + (uint32_t)((row * PAD + lc) * 4),
                          col_base + (long)(c * TILE_D + row) * VOCAB);
            }
        }
    };

    // Prologue: stages 0..STAGES-2, one commit group each.
    #pragma unroll
    for (int c = 0; c < STAGES - 1; c++) {
        issue_chunk(c);
        cp_commit();
    }

    for (int c = 0; c < N_CHUNK; c++) {
        cp_wait<STAGES - 2>();   // chunk c's group retired (<=2 pending)
        __syncthreads();         // all warps: chunk c visible; distribute(c-1) done
        if (c + STAGES - 1 < N_CHUNK) issue_chunk(c + STAGES - 1);
        cp_commit();             // possibly-empty group keeps wait count valid

        // Distribute chunk c: row = lane -> one coalesced 128B store per token.
        const float* sstage = &buf[(c & (STAGES - 1)) * STAGE_ELEMS];
        const int d0 = c * TILE_D;
        for (int s = slot_start + wid; s < slot_end; s += 8) {
            const int pk    = g_slots[s];
            const int col   = pk >> 16;
            const int token = pk & 0xFFFF;
            out[(long)token * D_MODEL + d0 + lane] = sstage[lane * PAD + col];
        }
    }
}

extern "C" void kernel_launch(void* const* d_in, const int* in_sizes, int n_in,
                              void* d_out, int out_size) {
    const int* ids = nullptr;
    const float* W = nullptr;
    for (int i = 0; i < n_in; i++) {
        if (in_sizes[i] == N_TOK) ids = (const int*)d_in[i];
        else if (in_sizes[i] == D_MODEL * VOCAB) W = (const float*)d_in[i];
    }
    float* out = (float*)d_out;

    prep_kernel<<<1, 1024>>>(ids);
    gather_tile_kernel<<<N_TILES, 256>>>(W, out);
}

// round 7
// speedup vs baseline: 1.5750x; 1.5750x over previous
#include <cuda_runtime.h>
#include <cuda_bf16.h>
#include <cstdint>

// Embedding gather: out[token, :] = W[:, ids[token]], W row-major [D_MODEL, VOCAB].
// R7: cp.async (LDGSTS rt~8cyc -> ~4.5TB/s ceiling with forced 4B ops due to
// odd VOCAB) replaced by register-staged LDG.32 (rt 1.82/SM -> ~20TB/s issue
// ceiling) + STS. Double-buffered regs and smem, one barrier per chunk.

#define VOCAB     50257
#define D_MODEL   1024
#define N_TOK     (4 * 4096)

#define TILE_C    64
#define TILE_BITS 6
#define N_TILES   ((VOCAB + TILE_C - 1) / TILE_C)   // 786
#define TILE_D    32
#define N_CHUNK   (D_MODEL / TILE_D)                // 32
#define PAD       (TILE_C + 1)                      // 65: conflict-free
#define STAGE_ELEMS (TILE_D * PAD)                  // 2080 floats

// Scratch (device globals; no allocation allowed).
__device__ int g_start[N_TILES + 1];
__device__ int g_slots[N_TOK];    // (col_in_tile << 16) | token_index

// ---------------- fused prep: hist + scan + scatter, one block ----------------
__global__ __launch_bounds__(1024, 1)
void prep_kernel(const int* __restrict__ ids) {
    __shared__ int s_hist[1024];
    __shared__ int s_off[N_TILES];
    const int t = threadIdx.x;

    s_hist[t] = 0;
    __syncthreads();

    int my_id[N_TOK / 1024];
    #pragma unroll
    for (int i = 0; i < N_TOK / 1024; i++) {
        my_id[i] = ids[t + i * 1024];
        atomicAdd(&s_hist[my_id[i] >> TILE_BITS], 1);
    }
    __syncthreads();

    const int mine = s_hist[t];
    #pragma unroll
    for (int off = 1; off < 1024; off <<= 1) {
        int v = (t >= off) ? s_hist[t - off] : 0;
        __syncthreads();
        s_hist[t] += v;
        __syncthreads();
    }
    const int excl = s_hist[t] - mine;
    if (t <= N_TILES) g_start[t] = excl;
    if (t < N_TILES)  s_off[t]  = excl;
    __syncthreads();

    #pragma unroll
    for (int i = 0; i < N_TOK / 1024; i++) {
        const int id  = my_id[i];
        const int pos = atomicAdd(&s_off[id >> TILE_BITS], 1);
        g_slots[pos] = ((id & (TILE_C - 1)) << 16) | (t + i * 1024);
    }
}

// ---------------- gather: one block per 64-column tile ----------------
__global__ __launch_bounds__(256, 6)
void gather_tile_kernel(const float* __restrict__ W, float* __restrict__ out) {
    const int tile = blockIdx.x;
    const int slot_start = g_start[tile];
    const int slot_end   = g_start[tile + 1];
    if (slot_start >= slot_end) return;

    __shared__ float buf[2][STAGE_ELEMS];

    const int tid  = threadIdx.x;
    const int lane = tid & 31;
    const int wid  = tid >> 5;                 // 8 warps
    const int c0   = tile * TILE_C;

    // Load mapping: lc = column 0..63, lr = row-phase 0..3; each warp's 32
    // lanes are contiguous columns -> every LDG/STS is a 128B contiguous op.
    const int lc = tid & (TILE_C - 1);
    const int lr = tid >> TILE_BITS;
    // Clamp OOB columns of the last tile (reads duplicate data; never
    // distributed since no token id >= VOCAB).
    const int gcol = min(c0 + lc, VOCAB - 1);
    const float* __restrict__ col_base = W + gcol;

    float rcur[8], rnext[8];

    // Prologue: load chunk 0 into regs.
    #pragma unroll
    for (int p = 0; p < 8; p++)
        rcur[p] = __ldg(col_base + (long)(p * 4 + lr) * VOCAB);

    for (int c = 0; c < N_CHUNK; c++) {
        // Issue chunk c+1 loads early (consumed next iteration).
        if (c + 1 < N_CHUNK) {
            #pragma unroll
            for (int p = 0; p < 8; p++)
                rnext[p] = __ldg(col_base + (long)((c + 1) * TILE_D + p * 4 + lr) * VOCAB);
        }

        // Stage chunk c to smem. Buffer-reuse safety: buf[c&1] last held
        // chunk c-2, distributed in iteration c-2 AFTER that iteration's
        // barrier; every warp passed iteration c-1's barrier before reaching
        // this STS, so all distribute(c-2) reads are complete.
        float* sstage = &buf[c & 1][0];
        #pragma unroll
        for (int p = 0; p < 8; p++)
            sstage[(p * 4 + lr) * PAD + lc] = rcur[p];
        __syncthreads();

        // Distribute chunk c: row = lane -> one coalesced 128B store/token.
        const int d0 = c * TILE_D;
        for (int s = slot_start + wid; s < slot_end; s += 8) {
            const int pk    = g_slots[s];
            const int col   = pk >> 16;
            const int token = pk & 0xFFFF;
            out[(long)token * D_MODEL + d0 + lane] = sstage[lane * PAD + col];
        }

        #pragma unroll
        for (int p = 0; p < 8; p++) rcur[p] = rnext[p];
    }
}

extern "C" void kernel_launch(void* const* d_in, const int* in_sizes, int n_in,
                              void* d_out, int out_size) {
    const int* ids = nullptr;
    const float* W = nullptr;
    for (int i = 0; i < n_in; i++) {
        if (in_sizes[i] == N_TOK) ids = (const int*)d_in[i];
        else if (in_sizes[i] == D_MODEL * VOCAB) W = (const float*)d_in[i];
    }
    float* out = (float*)d_out;

    prep_kernel<<<1, 1024>>>(ids);
    gather_tile_kernel<<<N_TILES, 256>>>(W, out);
}

// round 8
// speedup vs baseline: 1.7605x; 1.1178x over previous
#include <cuda_runtime.h>
#include <cuda_bf16.h>
#include <cstdint>

// Embedding gather: out[token, :] = W[:, ids[token]], W row-major [D_MODEL, VOCAB].
// R8: prep kernels eliminated. Each tile-block self-discovers its tokens by
// scanning the 64KB id array (L2-resident broadcast), overlapped with the
// chunk-0 DRAM loads. Inner loop identical to R7 (proven 5.3TB/s).

#define VOCAB     50257
#define D_MODEL   1024
#define N_TOK     (4 * 4096)

#define TILE_C    64
#define TILE_BITS 6
#define N_TILES   ((VOCAB + TILE_C - 1) / TILE_C)   // 786
#define TILE_D    32
#define N_CHUNK   (D_MODEL / TILE_D)                // 32
#define PAD       (TILE_C + 1)                      // 65: conflict-free
#define STAGE_ELEMS (TILE_D * PAD)                  // 2080 floats
#define CAP       2048                              // token list capacity

__global__ __launch_bounds__(256, 6)
void gather_tile_kernel(const int* __restrict__ ids,
                        const float* __restrict__ W,
                        float* __restrict__ out) {
    const int tile = blockIdx.x;

    __shared__ float buf[2][STAGE_ELEMS];
    __shared__ int   s_list[CAP];
    __shared__ int   s_cnt;

    const int tid  = threadIdx.x;
    const int lane = tid & 31;
    const int wid  = tid >> 5;                 // 8 warps
    const int c0   = tile * TILE_C;

    // Load mapping: lc = column 0..63, lr = row-phase 0..3; each warp's 32
    // lanes are contiguous columns -> every LDG/STS is a 128B contiguous op.
    const int lc = tid & (TILE_C - 1);
    const int lr = tid >> TILE_BITS;
    // Clamp OOB columns of last tile (never distributed: no id >= VOCAB).
    const int gcol = min(c0 + lc, VOCAB - 1);
    const float* __restrict__ col_base = W + gcol;

    if (tid == 0) s_cnt = 0;

    float rcur[8], rnext[8];

    // Prologue: issue chunk-0 DRAM loads first; the id-filter below runs in
    // their shadow.
    #pragma unroll
    for (int p = 0; p < 8; p++)
        rcur[p] = __ldg(col_base + (long)(p * 4 + lr) * VOCAB);

    __syncthreads();   // s_cnt = 0 visible

    // Filter: find tokens whose id falls in this tile. Order irrelevant.
    const int4* __restrict__ ids4 = (const int4*)ids;
    for (int i = tid; i < N_TOK / 4; i += 256) {
        const int4 v = ids4[i];
        const int base_tok = i * 4;
        #pragma unroll
        for (int k = 0; k < 4; k++) {
            const int id = (&v.x)[k];
            if ((id >> TILE_BITS) == tile) {
                const int pos = atomicAdd(&s_cnt, 1);
                if (pos < CAP)
                    s_list[pos] = ((id & (TILE_C - 1)) << 16) | (base_tok + k);
            }
        }
    }
    __syncthreads();

    const int cnt = s_cnt;
    if (cnt == 0) return;                     // uniform: whole block exits
    const bool overflow = (cnt > CAP);
    const int n = overflow ? 0 : cnt;         // fast path count

    for (int c = 0; c < N_CHUNK; c++) {
        // Issue chunk c+1 loads early (consumed next iteration).
        if (c + 1 < N_CHUNK) {
            #pragma unroll
            for (int p = 0; p < 8; p++)
                rnext[p] = __ldg(col_base + (long)((c + 1) * TILE_D + p * 4 + lr) * VOCAB);
        }

        // Stage chunk c to smem. Safe: buf[c&1] last distributed in iter c-2,
        // and every warp passed iter c-1's barrier before this STS.
        float* sstage = &buf[c & 1][0];
        #pragma unroll
        for (int p = 0; p < 8; p++)
            sstage[(p * 4 + lr) * PAD + lc] = rcur[p];
        __syncthreads();

        // Distribute chunk c: row = lane -> one coalesced 128B store/token.
        const int d0 = c * TILE_D;
        for (int s = wid; s < n; s += 8) {
            const int pk    = s_list[s];
            const int col   = pk >> 16;
            const int token = pk & 0xFFFF;
            out[(long)token * D_MODEL + d0 + lane] = sstage[lane * PAD + col];
        }
        if (overflow) {
            // Correct-for-any-input fallback: rescan all ids (never taken for
            // this workload; idempotent with the list path).
            for (int s = wid; s < N_TOK; s += 8) {
                const int id = __ldg(&ids[s]);
                if ((id >> TILE_BITS) == tile)
                    out[(long)s * D_MODEL + d0 + lane] =
                        sstage[lane * PAD + (id & (TILE_C - 1))];
            }
        }

        #pragma unroll
        for (int p = 0; p < 8; p++) rcur[p] = rnext[p];
    }
}

extern "C" void kernel_launch(void* const* d_in, const int* in_sizes, int n_in,
                              void* d_out, int out_size) {
    const int* ids = nullptr;
    const float* W = nullptr;
    for (int i = 0; i < n_in; i++) {
        if (in_sizes[i] == N_TOK) ids = (const int*)d_in[i];
        else if (in_sizes[i] == D_MODEL * VOCAB) W = (const float*)d_in[i];
    }
    float* out = (float*)d_out;

    gather_tile_kernel<<<N_TILES, 256>>>(ids, W, out);
}